// round 9
// baseline (speedup 1.0000x reference)
#include <cstdint>
#include <cuda_runtime.h>
#include <cuda_bf16.h>
#include <math.h>
#include <float.h>

// Problem constants
#define Bc    2
#define Hh    64
#define Ww    160
#define DIMc  256
#define NHc   8
#define HDc   32
#define Nn    (Hh * Ww)       // 10240 tokens per batch
#define Mrows (Bc * Nn)       // 20480 total rows
#define SCALEF 0.17677669529663687f   // 32^-0.5

// Static scratch
__device__ float g_q[Mrows * DIMc];
__device__ float g_k[Mrows * DIMc];
__device__ float g_v[Mrows * DIMc];
__device__ uint2 g_xs[Mrows * 128];       // X pre-split: 128 uint2{hi2,lo2} per row (1024 B)
__device__ uint2 g_hs[Mrows * 128];       // attn output pre-split, same layout
__device__ uint32_t g_wh[4 * 32768];      // W hi planes: [w][k][n/2] bf16x2
__device__ uint32_t g_wl[4 * 32768];      // W lo planes

// ---------------------------------------------------------------------------
// helpers
// ---------------------------------------------------------------------------
__device__ __forceinline__ uint32_t smem_to_u32(const void* smem_ptr) {
    uint32_t addr;
    asm("{ .reg .u64 tmp; cvta.to.shared.u64 tmp, %1; cvt.u32.u64 %0, tmp; }"
        : "=r"(addr) : "l"(smem_ptr));
    return addr;
}

// bf16 hi/lo split: h = packed {lo half: bf16(x), hi half: bf16(y)}, l = residues
__device__ __forceinline__ void bsplit(float x, float y, uint32_t& h, uint32_t& l) {
    asm("cvt.rn.bf16x2.f32 %0, %1, %2;" : "=r"(h) : "f"(y), "f"(x));
    float hx = __uint_as_float(h << 16);
    float hy = __uint_as_float(h & 0xffff0000u);
    asm("cvt.rn.bf16x2.f32 %0, %1, %2;" : "=r"(l) : "f"(y - hy), "f"(x - hx));
}

__device__ __forceinline__ void mma_bf16(float* c, const uint32_t* a,
                                         uint32_t b0, uint32_t b1) {
    asm volatile(
        "mma.sync.aligned.m16n8k16.row.col.f32.bf16.bf16.f32 "
        "{%0,%1,%2,%3},{%4,%5,%6,%7},{%8,%9},{%0,%1,%2,%3};"
        : "+f"(c[0]), "+f"(c[1]), "+f"(c[2]), "+f"(c[3])
        : "r"(a[0]), "r"(a[1]), "r"(a[2]), "r"(a[3]), "r"(b0), "r"(b1));
}

__device__ __forceinline__ void ldsm_x4_t(uint32_t* r, uint32_t addr) {
    asm volatile(
        "ldmatrix.sync.aligned.m8n8.x4.trans.shared.b16 {%0,%1,%2,%3}, [%4];"
        : "=r"(r[0]), "=r"(r[1]), "=r"(r[2]), "=r"(r[3]) : "r"(addr));
}

#define CP16(dst, src) \
    asm volatile("cp.async.cg.shared.global [%0], [%1], 16;" :: "r"(dst), "l"(src))
#define CP_COMMIT() asm volatile("cp.async.commit_group;")
#define CP_WAIT(n)  asm volatile("cp.async.wait_group %0;" :: "n"(n))

// ---------------------------------------------------------------------------
// Pre-split conversion kernels (memory-bound)
// ---------------------------------------------------------------------------
__global__ void __launch_bounds__(256)
conv_x(const float* __restrict__ x) {
    size_t id = (size_t)blockIdx.x * 256 + threadIdx.x;  // 0 .. Mrows*128-1
    float2 v = *reinterpret_cast<const float2*>(x + id * 2);
    uint32_t h, l;
    bsplit(v.x, v.y, h, l);
    g_xs[id] = make_uint2(h, l);
}

__global__ void __launch_bounds__(256)
conv_w(const float* __restrict__ Wq, const float* __restrict__ Wk,
       const float* __restrict__ Wv, const float* __restrict__ Wp) {
    const int w = blockIdx.y;
    const float* src = (w == 0) ? Wq : (w == 1) ? Wk : (w == 2) ? Wv : Wp;
    const int id = blockIdx.x * 256 + threadIdx.x;       // 0 .. 32767
    float2 v = *reinterpret_cast<const float2*>(src + (size_t)id * 2);
    uint32_t h, l;
    bsplit(v.x, v.y, h, l);
    g_wh[w * 32768 + id] = h;
    g_wl[w * 32768 + id] = l;
}

// ---------------------------------------------------------------------------
// bf16x3 GEMM with cp.async 3-stage pipeline.
// C[M x 256] = A[M x 256] @ W[256 x 256].  BM=64, BN=128, BK=32, 256 threads
// (8 warps: 2m x 4n, warp tile 32x32).  Operands pre-split in gmem.
// smem per stage: A 64x160B (interleaved hi/lo uint2 rows) + Bhi 32x272B + Blo.
// ---------------------------------------------------------------------------
#define A_ST   10240             // 64 * 160
#define BH_ST  8704              // 32 * 272
#define STAGE  27648             // A_ST + 2*BH_ST
#define SMEM_GEMM (3 * STAGE)    // 82944

// gmem A row = 128 uint2 = 1024 B; one stage = 32 k = 16 uint2 = 128 B
#define AROW_B 1024

__device__ __forceinline__ void issue_stage(
    uint32_t base, int s,
    const char* Ag, const char* Wh, const char* Wl,
    uint32_t ad0, uint32_t bd0)
{
    const char* a = Ag + s * 128;
    CP16(base + ad0, a);
    CP16(base + ad0 + 32 * 160, a + 32 * AROW_B);
    const char* wh = Wh + s * 16384;       // 32 k-rows * 512 B
    CP16(base + bd0, wh);
    CP16(base + bd0 + 16 * 272, wh + 16 * 512);
    const char* wl = Wl + s * 16384;
    CP16(base + bd0 + BH_ST, wl);
    CP16(base + bd0 + BH_ST + 16 * 272, wl + 16 * 512);
    CP_COMMIT();
}

__device__ __forceinline__ void gemm_body(const uint2* __restrict__ Asrc,
                                          const uint32_t* __restrict__ Whi,
                                          const uint32_t* __restrict__ Wlo,
                                          float* __restrict__ C) {
    extern __shared__ char smem_c[];
    const uint32_t sb = smem_to_u32(smem_c);
    const int t    = threadIdx.x;
    const int warp = t >> 5;
    const int lane = t & 31;
    const int q    = lane >> 2;
    const int c4   = lane & 3;
    const int bm = blockIdx.y * 64;
    const int bn = blockIdx.x * 128;
    const int wm = (warp >> 2) * 32;   // 0 or 32
    const int wn = (warp & 3) * 32;    // 0,32,64,96

    // staging source/dest (per thread: 2 A chunks, 2 Bhi, 2 Blo of 16 B)
    const char* Ag = (const char*)Asrc + (size_t)(bm + (t >> 3)) * AROW_B + (t & 7) * 16;
    const char* Wh = (const char*)Whi + (size_t)((t >> 4) * 256 + bn) * 2 + (t & 15) * 16;
    const char* Wl = (const char*)Wlo + (size_t)((t >> 4) * 256 + bn) * 2 + (t & 15) * 16;
    const uint32_t ad0 = (uint32_t)((t >> 3) * 160 + (t & 7) * 16);
    const uint32_t bd0 = (uint32_t)(A_ST + (t >> 4) * 272 + (t & 15) * 16);

    float acc[2][4][4];
#pragma unroll
    for (int i = 0; i < 2; i++)
#pragma unroll
        for (int j = 0; j < 4; j++)
#pragma unroll
            for (int e = 0; e < 4; e++) acc[i][j][e] = 0.f;

    issue_stage(sb,          0, Ag, Wh, Wl, ad0, bd0);
    issue_stage(sb + STAGE,  1, Ag, Wh, Wl, ad0, bd0);

#pragma unroll 1
    for (int s = 0; s < 8; s++) {
        const int buf = s % 3;
        if (s < 6) { CP_WAIT(1); } else { CP_WAIT(0); }
        __syncthreads();
        if (s < 6)
            issue_stage(sb + ((s + 2) % 3) * STAGE, s + 2, Ag, Wh, Wl, ad0, bd0);

        const char* Ab = smem_c + buf * STAGE;
        const uint32_t bhb = sb + buf * STAGE + A_ST;
        const uint32_t blb = bhb + BH_ST;

#pragma unroll
        for (int k16 = 0; k16 < 2; k16++) {
            uint32_t ah[2][4], al[2][4];
#pragma unroll
            for (int mt = 0; mt < 2; mt++) {
                const uint2* Ap = reinterpret_cast<const uint2*>(Ab)
                                + (wm + mt * 16 + q) * 20 + k16 * 8 + c4;
                uint2 u0 = Ap[0];
                uint2 u1 = Ap[160];
                uint2 u2 = Ap[4];
                uint2 u3 = Ap[164];
                ah[mt][0] = u0.x; al[mt][0] = u0.y;
                ah[mt][1] = u1.x; al[mt][1] = u1.y;
                ah[mt][2] = u2.x; al[mt][2] = u2.y;
                ah[mt][3] = u3.x; al[mt][3] = u3.y;
            }
            uint32_t bh[2][4], bl[2][4];
#pragma unroll
            for (int nc = 0; nc < 2; nc++) {
                uint32_t off = (uint32_t)((k16 * 16 + (lane & 15)) * 272
                              + (wn + nc * 16 + ((lane >> 4) << 3)) * 2);
                ldsm_x4_t(bh[nc], bhb + off);
                ldsm_x4_t(bl[nc], blb + off);
            }
#pragma unroll
            for (int mt = 0; mt < 2; mt++)
#pragma unroll
                for (int n8 = 0; n8 < 4; n8++) {
                    const int nc = n8 >> 1, jj = (n8 & 1) * 2;
                    mma_bf16(acc[mt][n8], ah[mt], bh[nc][jj], bh[nc][jj + 1]);
                    mma_bf16(acc[mt][n8], ah[mt], bl[nc][jj], bl[nc][jj + 1]);
                    mma_bf16(acc[mt][n8], al[mt], bh[nc][jj], bh[nc][jj + 1]);
                }
        }
        __syncthreads();
    }

    // epilogue
#pragma unroll
    for (int mt = 0; mt < 2; mt++) {
#pragma unroll
        for (int n8 = 0; n8 < 4; n8++) {
            const int gr0 = bm + wm + mt * 16 + q;
            const int gc  = bn + wn + n8 * 8 + 2 * c4;
            *reinterpret_cast<float2*>(C + (size_t)gr0 * DIMc + gc) =
                make_float2(acc[mt][n8][0], acc[mt][n8][1]);
            *reinterpret_cast<float2*>(C + (size_t)(gr0 + 8) * DIMc + gc) =
                make_float2(acc[mt][n8][2], acc[mt][n8][3]);
        }
    }
}

__global__ void __launch_bounds__(256, 2)
gemm_qkv() {
    const int z = blockIdx.z;
    float* C = (z == 0) ? g_q : (z == 1) ? g_k : g_v;
    gemm_body(g_xs, g_wh + z * 32768, g_wl + z * 32768, C);
}

__global__ void __launch_bounds__(256, 2)
gemm_proj(float* __restrict__ out) {
    gemm_body(g_hs, g_wh + 3 * 32768, g_wl + 3 * 32768, out);
}

// ---------------------------------------------------------------------------
// Attention: block per token, warp per head, lane = dim.
// Emits pre-split bf16 hi/lo output directly (proj consumes it).
// ---------------------------------------------------------------------------
__global__ void __launch_bounds__(256, 6)
attn_kernel(const float* __restrict__ mo) {
    const int r = blockIdx.x;
    const int b = (r >= Nn) ? 1 : 0;
    const int warp = threadIdx.x >> 5;
    const int lane = threadIdx.x & 31;

    float ox = mo[(size_t)r * 2 + 0];
    float oy = mo[(size_t)r * 2 + 1];
    ox = fminf(fmaxf(ox, 1.0f), (float)(Ww - 2) - 0.001f);
    oy = fminf(fmaxf(oy, 1.0f), (float)(Hh - 2) - 0.001f);
    const float mx = floorf(ox), my = floorf(oy);
    const float fx = ox - mx,   fy = oy - my;

    const int ibase = b * Nn + ((int)my - 1) * Ww + ((int)mx - 1);

    const size_t head_off = (size_t)warp * HDc + lane;
    const float qd = g_q[(size_t)r * DIMc + head_off] * SCALEF;

    float part[16];
#pragma unroll
    for (int a = 0; a < 16; a++) {
        int ia = ibase + (a >> 2) * Ww + (a & 3);
        part[a] = qd * g_k[(size_t)ia * DIMc + head_off];
    }

    // Multi-value butterfly reduction of the 16 dot products.
    float v8[8];
    {
        const bool hi = (lane & 16) != 0;
#pragma unroll
        for (int j = 0; j < 8; j++) {
            float send = hi ? part[j] : part[j + 8];
            float keep = hi ? part[j + 8] : part[j];
            v8[j] = keep + __shfl_xor_sync(0xffffffffu, send, 16);
        }
    }
    float v4[4];
    {
        const bool hi = (lane & 8) != 0;
#pragma unroll
        for (int j = 0; j < 4; j++) {
            float send = hi ? v8[j] : v8[j + 4];
            float keep = hi ? v8[j + 4] : v8[j];
            v4[j] = keep + __shfl_xor_sync(0xffffffffu, send, 8);
        }
    }
    float v2[2];
    {
        const bool hi = (lane & 4) != 0;
        float s0 = hi ? v4[2] : v4[0];
        float s1 = hi ? v4[3] : v4[1];
        float d0 = hi ? v4[0] : v4[2];
        float d1 = hi ? v4[1] : v4[3];
        v2[0] = s0 + __shfl_xor_sync(0xffffffffu, d0, 4);
        v2[1] = s1 + __shfl_xor_sync(0xffffffffu, d1, 4);
    }
    float v1;
    {
        const bool hi = (lane & 2) != 0;
        float keep = hi ? v2[1] : v2[0];
        float send = hi ? v2[0] : v2[1];
        v1 = keep + __shfl_xor_sync(0xffffffffu, send, 2);
    }
    float sfin = v1 + __shfl_xor_sync(0xffffffffu, v1, 1);
    float sa = __shfl_sync(0xffffffffu, sfin, (lane & 15) * 2);

    const int axp = lane & 3;
    const int ayp = (lane >> 2) & 3;
    const float wxv = (axp == 0) ? (1.f - fx) : ((axp == 3) ? fx : 1.f);
    const float wyv = (ayp == 0) ? (1.f - fy) : ((ayp == 3) ? fy : 1.f);
    const float bw = wxv * wyv;

    float mval = sa;
#pragma unroll
    for (int o = 8; o > 0; o >>= 1)
        mval = fmaxf(mval, __shfl_xor_sync(0xffffffffu, mval, o));
    float e = (lane < 16) ? __expf(sa - mval) * bw : 0.f;
    float se = e;
#pragma unroll
    for (int o = 16; o > 0; o >>= 1)
        se += __shfl_xor_sync(0xffffffffu, se, o);
    const float p = __fdividef(e, se);

    float accv = 0.f;
#pragma unroll
    for (int a = 0; a < 16; a++) {
        int ia = ibase + (a >> 2) * Ww + (a & 3);
        float va = g_v[(size_t)ia * DIMc + head_off];
        float pa = __shfl_sync(0xffffffffu, p, a);
        accv += pa * va;
    }

    // pack pairs of adjacent columns -> interleaved bf16 hi/lo
    float nb = __shfl_xor_sync(0xffffffffu, accv, 1);   // partner column's value
    if ((lane & 1) == 0) {
        uint32_t h, l;
        bsplit(accv, nb, h, l);
        g_hs[(size_t)r * 128 + (head_off >> 1)] = make_uint2(h, l);
    }
}

// ---------------------------------------------------------------------------
extern "C" void kernel_launch(void* const* d_in, const int* in_sizes, int n_in,
                              void* d_out, int out_size) {
    const float* x  = (const float*)d_in[0];
    const float* mo = (const float*)d_in[1];
    const float* Wq = (const float*)d_in[2];
    const float* Wk = (const float*)d_in[3];
    const float* Wv = (const float*)d_in[4];
    const float* Wp = (const float*)d_in[5];
    float* out = (float*)d_out;

    cudaFuncSetAttribute(gemm_qkv, cudaFuncAttributeMaxDynamicSharedMemorySize, SMEM_GEMM);
    cudaFuncSetAttribute(gemm_proj, cudaFuncAttributeMaxDynamicSharedMemorySize, SMEM_GEMM);

    conv_w<<<dim3(128, 4), 256>>>(Wq, Wk, Wv, Wp);
    conv_x<<<(Mrows * 128) / 256, 256>>>(x);
    gemm_qkv<<<dim3(2, Mrows / 64, 3), 256, SMEM_GEMM>>>();
    attn_kernel<<<Mrows, 256>>>(mo);
    gemm_proj<<<dim3(2, Mrows / 64), 256, SMEM_GEMM>>>(out);
}

// round 10
// speedup vs baseline: 1.1902x; 1.1902x over previous
#include <cstdint>
#include <cuda_runtime.h>
#include <cuda_bf16.h>
#include <math.h>
#include <float.h>

// Problem constants
#define Bc    2
#define Hh    64
#define Ww    160
#define DIMc  256
#define NHc   8
#define HDc   32
#define Nn    (Hh * Ww)       // 10240 tokens per batch
#define Mrows (Bc * Nn)       // 20480 total rows
#define SCALEF 0.17677669529663687f   // 32^-0.5

// Static scratch
__device__ float g_q[Mrows * DIMc];
__device__ float g_k[Mrows * DIMc];
__device__ float g_v[Mrows * DIMc];
__device__ uint2 g_xs[Mrows * 128];       // X pre-split: 128 uint2{hi2,lo2} per row
__device__ uint2 g_hs[Mrows * 128];       // attn output pre-split, same layout
__device__ uint32_t g_wh[4 * 32768];      // W hi planes: [w][k][n/2] bf16x2
__device__ uint32_t g_wl[4 * 32768];      // W lo planes

// ---------------------------------------------------------------------------
// helpers
// ---------------------------------------------------------------------------
__device__ __forceinline__ uint32_t smem_to_u32(const void* smem_ptr) {
    uint32_t addr;
    asm("{ .reg .u64 tmp; cvta.to.shared.u64 tmp, %1; cvt.u32.u64 %0, tmp; }"
        : "=r"(addr) : "l"(smem_ptr));
    return addr;
}

__device__ __forceinline__ void bsplit(float x, float y, uint32_t& h, uint32_t& l) {
    asm("cvt.rn.bf16x2.f32 %0, %1, %2;" : "=r"(h) : "f"(y), "f"(x));
    float hx = __uint_as_float(h << 16);
    float hy = __uint_as_float(h & 0xffff0000u);
    asm("cvt.rn.bf16x2.f32 %0, %1, %2;" : "=r"(l) : "f"(y - hy), "f"(x - hx));
}

__device__ __forceinline__ void mma_bf16(float* c, const uint32_t* a,
                                         uint32_t b0, uint32_t b1) {
    asm volatile(
        "mma.sync.aligned.m16n8k16.row.col.f32.bf16.bf16.f32 "
        "{%0,%1,%2,%3},{%4,%5,%6,%7},{%8,%9},{%0,%1,%2,%3};"
        : "+f"(c[0]), "+f"(c[1]), "+f"(c[2]), "+f"(c[3])
        : "r"(a[0]), "r"(a[1]), "r"(a[2]), "r"(a[3]), "r"(b0), "r"(b1));
}

__device__ __forceinline__ void ldsm_x4_t(uint32_t* r, uint32_t addr) {
    asm volatile(
        "ldmatrix.sync.aligned.m8n8.x4.trans.shared.b16 {%0,%1,%2,%3}, [%4];"
        : "=r"(r[0]), "=r"(r[1]), "=r"(r[2]), "=r"(r[3]) : "r"(addr));
}

#define CP16(dst, src) \
    asm volatile("cp.async.cg.shared.global [%0], [%1], 16;" :: "r"(dst), "l"(src))
#define CP_COMMIT() asm volatile("cp.async.commit_group;")
#define CP_WAIT(n)  asm volatile("cp.async.wait_group %0;" :: "n"(n))

// ---------------------------------------------------------------------------
// Pre-split conversion kernels
// ---------------------------------------------------------------------------
__global__ void __launch_bounds__(256)
conv_x(const float* __restrict__ x) {
    size_t id = (size_t)blockIdx.x * 256 + threadIdx.x;
    float2 v = *reinterpret_cast<const float2*>(x + id * 2);
    uint32_t h, l;
    bsplit(v.x, v.y, h, l);
    g_xs[id] = make_uint2(h, l);
}

__global__ void __launch_bounds__(256)
conv_w(const float* __restrict__ Wq, const float* __restrict__ Wk,
       const float* __restrict__ Wv, const float* __restrict__ Wp) {
    const int w = blockIdx.y;
    const float* src = (w == 0) ? Wq : (w == 1) ? Wk : (w == 2) ? Wv : Wp;
    const int id = blockIdx.x * 256 + threadIdx.x;
    float2 v = *reinterpret_cast<const float2*>(src + (size_t)id * 2);
    uint32_t h, l;
    bsplit(v.x, v.y, h, l);
    g_wh[w * 32768 + id] = h;
    g_wl[w * 32768 + id] = l;
}

// ---------------------------------------------------------------------------
// bf16x3 GEMM, cp.async, BK=64 stages (2 x k32 sub-chunks), 2 buffers.
// BM=64, BN=128, 256 threads (8 warps: 2m x 4n, warp tile 32x32).
// ---------------------------------------------------------------------------
#define A_ST   10240             // 64 rows * 160 B
#define BH_ST  8704              // 32 rows * 272 B
#define SUB    27648             // A_ST + 2*BH_ST
#define STAGE  55296             // 2 sub-chunks
#define SMEM_GEMM (2 * STAGE)    // 110592

#define AROW_B 1024              // gmem A row bytes (128 uint2)

__device__ __forceinline__ void issue_stage(
    uint32_t base, int s,
    const char* Ag, const char* Wh, const char* Wl,
    uint32_t ad0, uint32_t bd0)
{
#pragma unroll
    for (int c = 0; c < 2; c++) {
        const int g = s * 2 + c;                 // k32 chunk index 0..7
        const uint32_t sub = base + c * SUB;
        const char* a = Ag + g * 128;
        CP16(sub + ad0, a);
        CP16(sub + ad0 + 32 * 160, a + 32 * AROW_B);
        const char* wh = Wh + g * 16384;
        CP16(sub + bd0, wh);
        CP16(sub + bd0 + 16 * 272, wh + 16 * 512);
        const char* wl = Wl + g * 16384;
        CP16(sub + bd0 + BH_ST, wl);
        CP16(sub + bd0 + BH_ST + 16 * 272, wl + 16 * 512);
    }
    CP_COMMIT();
}

__device__ __forceinline__ void gemm_body(const uint2* __restrict__ Asrc,
                                          const uint32_t* __restrict__ Whi,
                                          const uint32_t* __restrict__ Wlo,
                                          float* __restrict__ C) {
    extern __shared__ char smem_c[];
    const uint32_t sb = smem_to_u32(smem_c);
    const int t    = threadIdx.x;
    const int warp = t >> 5;
    const int lane = t & 31;
    const int q    = lane >> 2;
    const int c4   = lane & 3;
    const int bm = blockIdx.y * 64;
    const int bn = blockIdx.x * 128;
    const int wm = (warp >> 2) * 32;
    const int wn = (warp & 3) * 32;

    const char* Ag = (const char*)Asrc + (size_t)(bm + (t >> 3)) * AROW_B + (t & 7) * 16;
    const char* Wh = (const char*)Whi + (size_t)((t >> 4) * 256 + bn) * 2 + (t & 15) * 16;
    const char* Wl = (const char*)Wlo + (size_t)((t >> 4) * 256 + bn) * 2 + (t & 15) * 16;
    const uint32_t ad0 = (uint32_t)((t >> 3) * 160 + (t & 7) * 16);
    const uint32_t bd0 = (uint32_t)(A_ST + (t >> 4) * 272 + (t & 15) * 16);

    float acc[2][4][4];
#pragma unroll
    for (int i = 0; i < 2; i++)
#pragma unroll
        for (int j = 0; j < 4; j++)
#pragma unroll
            for (int e = 0; e < 4; e++) acc[i][j][e] = 0.f;

    issue_stage(sb, 0, Ag, Wh, Wl, ad0, bd0);

#pragma unroll 1
    for (int s = 0; s < 4; s++) {
        if (s < 3) {
            issue_stage(sb + ((s + 1) & 1) * STAGE, s + 1, Ag, Wh, Wl, ad0, bd0);
            CP_WAIT(1);
        } else {
            CP_WAIT(0);
        }
        __syncthreads();

        const uint32_t bufb = sb + (s & 1) * STAGE;
        const char* bufc = smem_c + (s & 1) * STAGE;

#pragma unroll
        for (int c = 0; c < 2; c++) {
            const char* Ab = bufc + c * SUB;
            const uint32_t bhb = bufb + c * SUB + A_ST;
            const uint32_t blb = bhb + BH_ST;

#pragma unroll
            for (int k16 = 0; k16 < 2; k16++) {
                uint32_t ah[2][4], al[2][4];
#pragma unroll
                for (int mt = 0; mt < 2; mt++) {
                    const uint2* Ap = reinterpret_cast<const uint2*>(Ab)
                                    + (wm + mt * 16 + q) * 20 + k16 * 8 + c4;
                    uint2 u0 = Ap[0];
                    uint2 u1 = Ap[160];
                    uint2 u2 = Ap[4];
                    uint2 u3 = Ap[164];
                    ah[mt][0] = u0.x; al[mt][0] = u0.y;
                    ah[mt][1] = u1.x; al[mt][1] = u1.y;
                    ah[mt][2] = u2.x; al[mt][2] = u2.y;
                    ah[mt][3] = u3.x; al[mt][3] = u3.y;
                }
                uint32_t bh[2][4], bl[2][4];
#pragma unroll
                for (int nc = 0; nc < 2; nc++) {
                    uint32_t off = (uint32_t)((k16 * 16 + (lane & 15)) * 272
                                  + (wn + nc * 16 + ((lane >> 4) << 3)) * 2);
                    ldsm_x4_t(bh[nc], bhb + off);
                    ldsm_x4_t(bl[nc], blb + off);
                }
#pragma unroll
                for (int mt = 0; mt < 2; mt++)
#pragma unroll
                    for (int n8 = 0; n8 < 4; n8++) {
                        const int nc = n8 >> 1, jj = (n8 & 1) * 2;
                        mma_bf16(acc[mt][n8], ah[mt], bh[nc][jj], bh[nc][jj + 1]);
                        mma_bf16(acc[mt][n8], ah[mt], bl[nc][jj], bl[nc][jj + 1]);
                        mma_bf16(acc[mt][n8], al[mt], bh[nc][jj], bh[nc][jj + 1]);
                    }
            }
        }
        __syncthreads();
    }

    // epilogue
#pragma unroll
    for (int mt = 0; mt < 2; mt++) {
#pragma unroll
        for (int n8 = 0; n8 < 4; n8++) {
            const int gr0 = bm + wm + mt * 16 + q;
            const int gc  = bn + wn + n8 * 8 + 2 * c4;
            *reinterpret_cast<float2*>(C + (size_t)gr0 * DIMc + gc) =
                make_float2(acc[mt][n8][0], acc[mt][n8][1]);
            *reinterpret_cast<float2*>(C + (size_t)(gr0 + 8) * DIMc + gc) =
                make_float2(acc[mt][n8][2], acc[mt][n8][3]);
        }
    }
}

__global__ void __launch_bounds__(256, 2)
gemm_qkv() {
    const int z = blockIdx.z;
    float* C = (z == 0) ? g_q : (z == 1) ? g_k : g_v;
    gemm_body(g_xs, g_wh + z * 32768, g_wl + z * 32768, C);
}

__global__ void __launch_bounds__(256, 2)
gemm_proj(float* __restrict__ out) {
    gemm_body(g_hs, g_wh + 3 * 32768, g_wl + 3 * 32768, out);
}

// ---------------------------------------------------------------------------
// Attention v2: float2-vectorized. Warp = head. lane = (dim-pair hl, side).
// Each LDG.64 fetches 2 dims of 1 position; 32 lanes cover 2 positions/load.
// Position of lane for loads i=0..7: a = 2*i + side.
// After the half-butterfly, lane l holds score S_a with a = 2*((l>>1)&7)+(l>>4).
// ---------------------------------------------------------------------------
__global__ void __launch_bounds__(256, 6)
attn_kernel(const float* __restrict__ mo) {
    const int r = blockIdx.x;
    const int bofs = (r >= Nn) ? Nn : 0;
    const int h = threadIdx.x >> 5;
    const int lane = threadIdx.x & 31;
    const int hl = lane & 15;        // dim pair index (dims 2*hl, 2*hl+1)
    const int side = lane >> 4;      // position parity

    float ox = mo[(size_t)r * 2 + 0];
    float oy = mo[(size_t)r * 2 + 1];
    ox = fminf(fmaxf(ox, 1.0f), (float)(Ww - 2) - 0.001f);
    oy = fminf(fmaxf(oy, 1.0f), (float)(Hh - 2) - 0.001f);
    const float mx = floorf(ox), my = floorf(oy);
    const float fx = ox - mx,   fy = oy - my;

    const int ibase = bofs + ((int)my - 1) * Ww + ((int)mx - 1);

    const float2 q2 = *reinterpret_cast<const float2*>(
        g_q + (size_t)r * DIMc + h * HDc + hl * 2);
    const float qd0 = q2.x * SCALEF, qd1 = q2.y * SCALEF;

    const float2* kbase = reinterpret_cast<const float2*>(
        g_k + (size_t)ibase * DIMc + h * HDc + hl * 2);
    const float2* vbase = reinterpret_cast<const float2*>(
        g_v + (size_t)ibase * DIMc + h * HDc + hl * 2);

    int roff[8];
    float part[8];
#pragma unroll
    for (int i = 0; i < 8; i++) {
        int a = 2 * i + side;
        roff[i] = (a >> 2) * Ww + (a & 3);
        float2 k2 = kbase[(size_t)roff[i] * 128];
        part[i] = qd0 * k2.x + qd1 * k2.y;
    }

    // 8-value butterfly within 16-lane halves (offsets 8,4,2,1)
    float w4[4];
    {
        const bool hi = (lane & 8) != 0;
#pragma unroll
        for (int j = 0; j < 4; j++) {
            float keep = hi ? part[j + 4] : part[j];
            float send = hi ? part[j] : part[j + 4];
            w4[j] = keep + __shfl_xor_sync(0xffffffffu, send, 8);
        }
    }
    float w2[2];
    {
        const bool hi = (lane & 4) != 0;
#pragma unroll
        for (int j = 0; j < 2; j++) {
            float keep = hi ? w4[j + 2] : w4[j];
            float send = hi ? w4[j] : w4[j + 2];
            w2[j] = keep + __shfl_xor_sync(0xffffffffu, send, 4);
        }
    }
    float w1;
    {
        const bool hi = (lane & 2) != 0;
        float keep = hi ? w2[1] : w2[0];
        float send = hi ? w2[0] : w2[1];
        w1 = keep + __shfl_xor_sync(0xffffffffu, send, 2);
    }
    const float s = w1 + __shfl_xor_sync(0xffffffffu, w1, 1);
    // lane holds S_a, a = 2*((lane>>1)&7) + side

    const int a_mine = 2 * ((lane >> 1) & 7) + side;
    const int axp = a_mine & 3;
    const int ayp = a_mine >> 2;
    const float wxv = (axp == 0) ? (1.f - fx) : ((axp == 3) ? fx : 1.f);
    const float wyv = (ayp == 0) ? (1.f - fy) : ((ayp == 3) ? fy : 1.f);
    const float bw = wxv * wyv;

    // softmax over 16 positions (each represented twice across the warp)
    float mval = s;
#pragma unroll
    for (int o = 16; o > 0; o >>= 1)
        mval = fmaxf(mval, __shfl_xor_sync(0xffffffffu, mval, o));
    const float e = __expf(s - mval) * bw;
    float se = e;
#pragma unroll
    for (int o = 16; o > 0; o >>= 1)
        se += __shfl_xor_sync(0xffffffffu, se, o);
    const float p = __fdividef(e, 0.5f * se);   // se double-counts every a

    // V accumulate: p for position a_i=2i+side lives in lane (lane&16)|(i<<1)
    float ax = 0.f, ay = 0.f;
#pragma unroll
    for (int i = 0; i < 8; i++) {
        float2 v2 = vbase[(size_t)roff[i] * 128];
        float pa = __shfl_sync(0xffffffffu, p, (lane & 16) | (i << 1));
        ax += pa * v2.x;
        ay += pa * v2.y;
    }
    ax += __shfl_xor_sync(0xffffffffu, ax, 16);
    ay += __shfl_xor_sync(0xffffffffu, ay, 16);

    if (side == 0) {
        uint32_t hb, lb;
        bsplit(ax, ay, hb, lb);
        g_hs[(size_t)r * 128 + h * 16 + hl] = make_uint2(hb, lb);
    }
}

// ---------------------------------------------------------------------------
extern "C" void kernel_launch(void* const* d_in, const int* in_sizes, int n_in,
                              void* d_out, int out_size) {
    const float* x  = (const float*)d_in[0];
    const float* mo = (const float*)d_in[1];
    const float* Wq = (const float*)d_in[2];
    const float* Wk = (const float*)d_in[3];
    const float* Wv = (const float*)d_in[4];
    const float* Wp = (const float*)d_in[5];
    float* out = (float*)d_out;

    cudaFuncSetAttribute(gemm_qkv, cudaFuncAttributeMaxDynamicSharedMemorySize, SMEM_GEMM);
    cudaFuncSetAttribute(gemm_proj, cudaFuncAttributeMaxDynamicSharedMemorySize, SMEM_GEMM);

    conv_w<<<dim3(128, 4), 256>>>(Wq, Wk, Wv, Wp);
    conv_x<<<(Mrows * 128) / 256, 256>>>(x);
    gemm_qkv<<<dim3(2, Mrows / 64, 3), 256, SMEM_GEMM>>>();
    attn_kernel<<<Mrows, 256>>>(mo);
    gemm_proj<<<dim3(2, Mrows / 64), 256, SMEM_GEMM>>>(out);
}

// round 11
// speedup vs baseline: 1.2195x; 1.0246x over previous
#include <cstdint>
#include <cuda_runtime.h>
#include <cuda_bf16.h>
#include <cuda_fp16.h>
#include <math.h>
#include <float.h>

// Problem constants
#define Bc    2
#define Hh    64
#define Ww    160
#define DIMc  256
#define NHc   8
#define HDc   32
#define Nn    (Hh * Ww)       // 10240 tokens per batch
#define Mrows (Bc * Nn)       // 20480 total rows
#define SCALEF 0.17677669529663687f   // 32^-0.5

// Static scratch
__device__ float    g_q [Mrows * DIMc];   // q, pre-scaled by SCALEF
__device__ uint32_t g_kh[Mrows * 128];    // k as half2 (2 dims per word)
__device__ uint32_t g_vh[Mrows * 128];    // v as half2
__device__ uint2    g_xs[Mrows * 128];    // X pre-split bf16 hi/lo
__device__ uint2    g_hs[Mrows * 128];    // attn output pre-split bf16 hi/lo
__device__ uint32_t g_wh[4 * 32768];      // W hi planes
__device__ uint32_t g_wl[4 * 32768];      // W lo planes

// ---------------------------------------------------------------------------
// helpers
// ---------------------------------------------------------------------------
__device__ __forceinline__ uint32_t smem_to_u32(const void* smem_ptr) {
    uint32_t addr;
    asm("{ .reg .u64 tmp; cvta.to.shared.u64 tmp, %1; cvt.u32.u64 %0, tmp; }"
        : "=r"(addr) : "l"(smem_ptr));
    return addr;
}

__device__ __forceinline__ void bsplit(float x, float y, uint32_t& h, uint32_t& l) {
    asm("cvt.rn.bf16x2.f32 %0, %1, %2;" : "=r"(h) : "f"(y), "f"(x));
    float hx = __uint_as_float(h << 16);
    float hy = __uint_as_float(h & 0xffff0000u);
    asm("cvt.rn.bf16x2.f32 %0, %1, %2;" : "=r"(l) : "f"(y - hy), "f"(x - hx));
}

__device__ __forceinline__ uint32_t f2h2(float x, float y) {   // lo=x, hi=y
    uint32_t u;
    asm("cvt.rn.f16x2.f32 %0, %1, %2;" : "=r"(u) : "f"(y), "f"(x));
    return u;
}

__device__ __forceinline__ void mma_bf16(float* c, const uint32_t* a,
                                         uint32_t b0, uint32_t b1) {
    asm volatile(
        "mma.sync.aligned.m16n8k16.row.col.f32.bf16.bf16.f32 "
        "{%0,%1,%2,%3},{%4,%5,%6,%7},{%8,%9},{%0,%1,%2,%3};"
        : "+f"(c[0]), "+f"(c[1]), "+f"(c[2]), "+f"(c[3])
        : "r"(a[0]), "r"(a[1]), "r"(a[2]), "r"(a[3]), "r"(b0), "r"(b1));
}

__device__ __forceinline__ void ldsm_x4_t(uint32_t* r, uint32_t addr) {
    asm volatile(
        "ldmatrix.sync.aligned.m8n8.x4.trans.shared.b16 {%0,%1,%2,%3}, [%4];"
        : "=r"(r[0]), "=r"(r[1]), "=r"(r[2]), "=r"(r[3]) : "r"(addr));
}

#define CP16(dst, src) \
    asm volatile("cp.async.cg.shared.global [%0], [%1], 16;" :: "r"(dst), "l"(src))
#define CP_COMMIT() asm volatile("cp.async.commit_group;")
#define CP_WAIT(n)  asm volatile("cp.async.wait_group %0;" :: "n"(n))

// ---------------------------------------------------------------------------
// Pre-split conversion kernels
// ---------------------------------------------------------------------------
__global__ void __launch_bounds__(256)
conv_x(const float* __restrict__ x) {
    size_t id = (size_t)blockIdx.x * 256 + threadIdx.x;
    float2 v = *reinterpret_cast<const float2*>(x + id * 2);
    uint32_t h, l;
    bsplit(v.x, v.y, h, l);
    g_xs[id] = make_uint2(h, l);
}

__global__ void __launch_bounds__(256)
conv_w(const float* __restrict__ Wq, const float* __restrict__ Wk,
       const float* __restrict__ Wv, const float* __restrict__ Wp) {
    const int w = blockIdx.y;
    const float* src = (w == 0) ? Wq : (w == 1) ? Wk : (w == 2) ? Wv : Wp;
    const int id = blockIdx.x * 256 + threadIdx.x;
    float2 v = *reinterpret_cast<const float2*>(src + (size_t)id * 2);
    uint32_t h, l;
    bsplit(v.x, v.y, h, l);
    g_wh[w * 32768 + id] = h;
    g_wl[w * 32768 + id] = l;
}

// ---------------------------------------------------------------------------
// bf16x3 GEMM, cp.async, BK=64 stages, 2 buffers.
// BM=64, BN=128, 256 threads (8 warps: 2m x 4n, warp tile 32x32).
// Epilogue: fp32 (scaled) OR packed half2 output.
// ---------------------------------------------------------------------------
#define A_ST   10240
#define BH_ST  8704
#define SUB    27648
#define STAGE  55296
#define SMEM_GEMM (2 * STAGE)
#define AROW_B 1024

__device__ __forceinline__ void issue_stage(
    uint32_t base, int s,
    const char* Ag, const char* Wh, const char* Wl,
    uint32_t ad0, uint32_t bd0)
{
#pragma unroll
    for (int c = 0; c < 2; c++) {
        const int g = s * 2 + c;
        const uint32_t sub = base + c * SUB;
        const char* a = Ag + g * 128;
        CP16(sub + ad0, a);
        CP16(sub + ad0 + 32 * 160, a + 32 * AROW_B);
        const char* wh = Wh + g * 16384;
        CP16(sub + bd0, wh);
        CP16(sub + bd0 + 16 * 272, wh + 16 * 512);
        const char* wl = Wl + g * 16384;
        CP16(sub + bd0 + BH_ST, wl);
        CP16(sub + bd0 + BH_ST + 16 * 272, wl + 16 * 512);
    }
    CP_COMMIT();
}

__device__ __forceinline__ void gemm_body(const uint2* __restrict__ Asrc,
                                          const uint32_t* __restrict__ Whi,
                                          const uint32_t* __restrict__ Wlo,
                                          float* __restrict__ Cf,
                                          uint32_t* __restrict__ Ch,
                                          float qscale) {
    extern __shared__ char smem_c[];
    const uint32_t sb = smem_to_u32(smem_c);
    const int t    = threadIdx.x;
    const int warp = t >> 5;
    const int lane = t & 31;
    const int q    = lane >> 2;
    const int c4   = lane & 3;
    const int bm = blockIdx.y * 64;
    const int bn = blockIdx.x * 128;
    const int wm = (warp >> 2) * 32;
    const int wn = (warp & 3) * 32;

    const char* Ag = (const char*)Asrc + (size_t)(bm + (t >> 3)) * AROW_B + (t & 7) * 16;
    const char* Wh = (const char*)Whi + (size_t)((t >> 4) * 256 + bn) * 2 + (t & 15) * 16;
    const char* Wl = (const char*)Wlo + (size_t)((t >> 4) * 256 + bn) * 2 + (t & 15) * 16;
    const uint32_t ad0 = (uint32_t)((t >> 3) * 160 + (t & 7) * 16);
    const uint32_t bd0 = (uint32_t)(A_ST + (t >> 4) * 272 + (t & 15) * 16);

    float acc[2][4][4];
#pragma unroll
    for (int i = 0; i < 2; i++)
#pragma unroll
        for (int j = 0; j < 4; j++)
#pragma unroll
            for (int e = 0; e < 4; e++) acc[i][j][e] = 0.f;

    issue_stage(sb, 0, Ag, Wh, Wl, ad0, bd0);

#pragma unroll 1
    for (int s = 0; s < 4; s++) {
        if (s < 3) {
            issue_stage(sb + ((s + 1) & 1) * STAGE, s + 1, Ag, Wh, Wl, ad0, bd0);
            CP_WAIT(1);
        } else {
            CP_WAIT(0);
        }
        __syncthreads();

        const uint32_t bufb = sb + (s & 1) * STAGE;
        const char* bufc = smem_c + (s & 1) * STAGE;

#pragma unroll
        for (int c = 0; c < 2; c++) {
            const char* Ab = bufc + c * SUB;
            const uint32_t bhb = bufb + c * SUB + A_ST;
            const uint32_t blb = bhb + BH_ST;

#pragma unroll
            for (int k16 = 0; k16 < 2; k16++) {
                uint32_t ah[2][4], al[2][4];
#pragma unroll
                for (int mt = 0; mt < 2; mt++) {
                    const uint2* Ap = reinterpret_cast<const uint2*>(Ab)
                                    + (wm + mt * 16 + q) * 20 + k16 * 8 + c4;
                    uint2 u0 = Ap[0];
                    uint2 u1 = Ap[160];
                    uint2 u2 = Ap[4];
                    uint2 u3 = Ap[164];
                    ah[mt][0] = u0.x; al[mt][0] = u0.y;
                    ah[mt][1] = u1.x; al[mt][1] = u1.y;
                    ah[mt][2] = u2.x; al[mt][2] = u2.y;
                    ah[mt][3] = u3.x; al[mt][3] = u3.y;
                }
                uint32_t bh[2][4], bl[2][4];
#pragma unroll
                for (int nc = 0; nc < 2; nc++) {
                    uint32_t off = (uint32_t)((k16 * 16 + (lane & 15)) * 272
                                  + (wn + nc * 16 + ((lane >> 4) << 3)) * 2);
                    ldsm_x4_t(bh[nc], bhb + off);
                    ldsm_x4_t(bl[nc], blb + off);
                }
#pragma unroll
                for (int mt = 0; mt < 2; mt++)
#pragma unroll
                    for (int n8 = 0; n8 < 4; n8++) {
                        const int nc = n8 >> 1, jj = (n8 & 1) * 2;
                        mma_bf16(acc[mt][n8], ah[mt], bh[nc][jj], bh[nc][jj + 1]);
                        mma_bf16(acc[mt][n8], ah[mt], bl[nc][jj], bl[nc][jj + 1]);
                        mma_bf16(acc[mt][n8], al[mt], bh[nc][jj], bh[nc][jj + 1]);
                    }
            }
        }
        __syncthreads();
    }

    // epilogue
    if (Ch) {
#pragma unroll
        for (int mt = 0; mt < 2; mt++) {
#pragma unroll
            for (int n8 = 0; n8 < 4; n8++) {
                const int gr0 = bm + wm + mt * 16 + q;
                const int gc  = bn + wn + n8 * 8 + 2 * c4;
                Ch[(size_t)gr0 * 128 + (gc >> 1)] =
                    f2h2(acc[mt][n8][0], acc[mt][n8][1]);
                Ch[(size_t)(gr0 + 8) * 128 + (gc >> 1)] =
                    f2h2(acc[mt][n8][2], acc[mt][n8][3]);
            }
        }
    } else {
#pragma unroll
        for (int mt = 0; mt < 2; mt++) {
#pragma unroll
            for (int n8 = 0; n8 < 4; n8++) {
                const int gr0 = bm + wm + mt * 16 + q;
                const int gc  = bn + wn + n8 * 8 + 2 * c4;
                *reinterpret_cast<float2*>(Cf + (size_t)gr0 * DIMc + gc) =
                    make_float2(acc[mt][n8][0] * qscale, acc[mt][n8][1] * qscale);
                *reinterpret_cast<float2*>(Cf + (size_t)(gr0 + 8) * DIMc + gc) =
                    make_float2(acc[mt][n8][2] * qscale, acc[mt][n8][3] * qscale);
            }
        }
    }
}

__global__ void __launch_bounds__(256, 2)
gemm_qkv() {
    const int z = blockIdx.z;
    if (z == 0)      gemm_body(g_xs, g_wh,           g_wl,           g_q, nullptr, SCALEF);
    else if (z == 1) gemm_body(g_xs, g_wh + 32768,   g_wl + 32768,   nullptr, g_kh, 1.f);
    else             gemm_body(g_xs, g_wh + 65536,   g_wl + 65536,   nullptr, g_vh, 1.f);
}

__global__ void __launch_bounds__(256, 2)
gemm_proj(float* __restrict__ out) {
    gemm_body(g_hs, g_wh + 3 * 32768, g_wl + 3 * 32768, out, nullptr, 1.f);
}

// ---------------------------------------------------------------------------
// Attention v3: fp16 K/V, 4 dims per lane, 4 position-groups per warp.
// lane = (g = lane&7 -> dims 4g..4g+3, sd = lane>>3 -> window column dx).
// Load i covers position a = 4*i + sd (row dy=i, col dx=sd).
// After butterfly (offsets 4,2,1), lane holds score for i=(lane>>1)&3.
// ---------------------------------------------------------------------------
__global__ void __launch_bounds__(256, 6)
attn_kernel(const float* __restrict__ mo) {
    const int r = blockIdx.x;
    const int bofs = (r >= Nn) ? Nn : 0;
    const int hd = threadIdx.x >> 5;      // head
    const int lane = threadIdx.x & 31;
    const int g  = lane & 7;              // dim group (4 dims)
    const int sd = lane >> 3;             // window column 0..3

    float2 o2 = *reinterpret_cast<const float2*>(mo + (size_t)r * 2);
    float ox = fminf(fmaxf(o2.x, 1.0f), (float)(Ww - 2) - 0.001f);
    float oy = fminf(fmaxf(o2.y, 1.0f), (float)(Hh - 2) - 0.001f);
    const float mx = floorf(ox), my = floorf(oy);
    const float fx = ox - mx,   fy = oy - my;

    const int ibase = bofs + ((int)my - 1) * Ww + ((int)mx - 1);

    // q: 4 dims (pre-scaled by SCALEF at GEMM epilogue)
    const float4 q4 = *reinterpret_cast<const float4*>(
        g_q + (size_t)r * DIMc + hd * HDc + g * 4);

    const uint32_t* kp = g_kh + (size_t)ibase * 128 + hd * 16 + g * 2;
    const uint32_t* vp = g_vh + (size_t)ibase * 128 + hd * 16 + g * 2;

    int roff[4];
    float part[4];
#pragma unroll
    for (int i = 0; i < 4; i++) {
        roff[i] = (i * Ww + sd) * 128;
        uint2 kk = *reinterpret_cast<const uint2*>(kp + roff[i]);
        float2 k01 = __half22float2(*reinterpret_cast<const __half2*>(&kk.x));
        float2 k23 = __half22float2(*reinterpret_cast<const __half2*>(&kk.y));
        part[i] = q4.x * k01.x + q4.y * k01.y + q4.z * k23.x + q4.w * k23.y;
    }

    // 4-value butterfly within 8-lane groups (offsets 4,2,1)
    float u2[2];
    {
        const bool hb = (lane & 4) != 0;
#pragma unroll
        for (int j = 0; j < 2; j++) {
            float keep = hb ? part[j + 2] : part[j];
            float send = hb ? part[j] : part[j + 2];
            u2[j] = keep + __shfl_xor_sync(0xffffffffu, send, 4);
        }
    }
    float u1;
    {
        const bool hb = (lane & 2) != 0;
        float keep = hb ? u2[1] : u2[0];
        float send = hb ? u2[0] : u2[1];
        u1 = keep + __shfl_xor_sync(0xffffffffu, send, 2);
    }
    const float s = u1 + __shfl_xor_sync(0xffffffffu, u1, 1);
    // lane holds score of position a = 4*i_mine + sd, i_mine = (lane>>1)&3

    const int i_mine = (lane >> 1) & 3;
    const float wxv = (sd == 0) ? (1.f - fx) : ((sd == 3) ? fx : 1.f);
    const float wyv = (i_mine == 0) ? (1.f - fy) : ((i_mine == 3) ? fy : 1.f);
    const float bw = wxv * wyv;

    // softmax over 16 positions (each represented twice across the warp)
    float mval = s;
#pragma unroll
    for (int o = 16; o > 0; o >>= 1)
        mval = fmaxf(mval, __shfl_xor_sync(0xffffffffu, mval, o));
    const float e = __expf(s - mval) * bw;
    float se = e;
#pragma unroll
    for (int o = 16; o > 0; o >>= 1)
        se += __shfl_xor_sync(0xffffffffu, se, o);
    const float p = __fdividef(e, 0.5f * se);

    // V accumulate (4 dims), p for a=4i+sd lives in lane (sd<<3)|(i<<1)
    float f0 = 0.f, f1 = 0.f, f2 = 0.f, f3 = 0.f;
#pragma unroll
    for (int i = 0; i < 4; i++) {
        uint2 vv = *reinterpret_cast<const uint2*>(vp + roff[i]);
        float2 v01 = __half22float2(*reinterpret_cast<const __half2*>(&vv.x));
        float2 v23 = __half22float2(*reinterpret_cast<const __half2*>(&vv.y));
        float pa = __shfl_sync(0xffffffffu, p, (lane & 24) | (i << 1));
        f0 += pa * v01.x;
        f1 += pa * v01.y;
        f2 += pa * v23.x;
        f3 += pa * v23.y;
    }
    // combine across the 4 sd groups
#pragma unroll
    for (int o = 8; o <= 16; o <<= 1) {
        f0 += __shfl_xor_sync(0xffffffffu, f0, o);
        f1 += __shfl_xor_sync(0xffffffffu, f1, o);
        f2 += __shfl_xor_sync(0xffffffffu, f2, o);
        f3 += __shfl_xor_sync(0xffffffffu, f3, o);
    }

    if (sd == 0) {
        uint32_t h0, l0, h1, l1;
        bsplit(f0, f1, h0, l0);
        bsplit(f2, f3, h1, l1);
        *reinterpret_cast<uint4*>(g_hs + (size_t)r * 128 + hd * 16 + g * 2) =
            make_uint4(h0, l0, h1, l1);
    }
}

// ---------------------------------------------------------------------------
extern "C" void kernel_launch(void* const* d_in, const int* in_sizes, int n_in,
                              void* d_out, int out_size) {
    const float* x  = (const float*)d_in[0];
    const float* mo = (const float*)d_in[1];
    const float* Wq = (const float*)d_in[2];
    const float* Wk = (const float*)d_in[3];
    const float* Wv = (const float*)d_in[4];
    const float* Wp = (const float*)d_in[5];
    float* out = (float*)d_out;

    cudaFuncSetAttribute(gemm_qkv, cudaFuncAttributeMaxDynamicSharedMemorySize, SMEM_GEMM);
    cudaFuncSetAttribute(gemm_proj, cudaFuncAttributeMaxDynamicSharedMemorySize, SMEM_GEMM);

    conv_w<<<dim3(128, 4), 256>>>(Wq, Wk, Wv, Wp);
    conv_x<<<(Mrows * 128) / 256, 256>>>(x);
    gemm_qkv<<<dim3(2, Mrows / 64, 3), 256, SMEM_GEMM>>>();
    attn_kernel<<<Mrows, 256>>>(mo);
    gemm_proj<<<dim3(2, Mrows / 64), 256, SMEM_GEMM>>>(out);
}